// round 13
// baseline (speedup 1.0000x reference)
#include <cuda_runtime.h>
#include <math.h>

#define B_ROWS 65536
#define C_COLS 1000
#define ROWS_PER_TILE 4
#define TILE_FLOATS (ROWS_PER_TILE * C_COLS)     // 4000
#define TILE_BYTES  (TILE_FLOATS * 4)            // 16000 per tensor
#define NTILES (B_ROWS / ROWS_PER_TILE)          // 16384
#define GRID_P 456                                // 3 CTAs/SM x 152 SMs
#define LOG2E_F 1.4426950408889634f

// Dynamic smem layout (bytes):
//   stage s in {0,1}: o at s*2*TILE_BYTES, t at s*2*TILE_BYTES + TILE_BYTES
//   bars at 4*TILE_BYTES (2 x u64), red at 4*TILE_BYTES + 16 (8x8 floats)
#define SMEM_BARS_OFF (4 * TILE_BYTES)
#define SMEM_RED_OFF  (SMEM_BARS_OFF + 16)
#define SMEM_DYN      (SMEM_RED_OFF + 8 * 8 * 4)

__device__ float g_partial[512];

typedef unsigned long long ull;

__device__ __forceinline__ ull pk2(float lo, float hi) {
    ull r; asm("mov.b64 %0, {%1, %2};" : "=l"(r) : "f"(lo), "f"(hi)); return r;
}
__device__ __forceinline__ void upk2(ull v, float& lo, float& hi) {
    asm("mov.b64 {%0, %1}, %2;" : "=f"(lo), "=f"(hi) : "l"(v));
}
__device__ __forceinline__ ull mul2(ull a, ull b) {
    ull d; asm("mul.rn.f32x2 %0, %1, %2;" : "=l"(d) : "l"(a), "l"(b)); return d;
}
__device__ __forceinline__ ull add2(ull a, ull b) {
    ull d; asm("add.rn.f32x2 %0, %1, %2;" : "=l"(d) : "l"(a), "l"(b)); return d;
}
__device__ __forceinline__ ull fma2(ull a, ull b, ull c) {
    ull d; asm("fma.rn.f32x2 %0, %1, %2, %3;" : "=l"(d) : "l"(a), "l"(b), "l"(c)); return d;
}
__device__ __forceinline__ float ex2f(float x) {
    float r; asm("ex2.approx.ftz.f32 %0, %1;" : "=f"(r) : "f"(x)); return r;
}
__device__ __forceinline__ unsigned smem_u32(const void* p) {
    unsigned a;
    asm("{ .reg .u64 t; cvta.to.shared.u64 t, %1; cvt.u32.u64 %0, t; }" : "=r"(a) : "l"(p));
    return a;
}
__device__ __forceinline__ float warpSum(float v) {
    #pragma unroll
    for (int k = 16; k; k >>= 1) v += __shfl_xor_sync(0xffffffffu, v, k);
    return v;
}
__device__ __forceinline__ void mbar_wait(unsigned mbar, unsigned parity) {
    unsigned done;
    asm volatile(
        "{\n\t.reg .pred p;\n\t"
        "mbarrier.try_wait.parity.acquire.cta.shared::cta.b64 p, [%1], %2;\n\t"
        "selp.b32 %0, 1, 0, p;\n\t}"
        : "=r"(done) : "r"(mbar), "r"(parity) : "memory");
    if (!done) {
        asm volatile(
            "{\n\t.reg .pred P1;\n\t"
            "WL_%=:\n\t"
            "mbarrier.try_wait.parity.acquire.cta.shared::cta.b64 P1, [%0], %1, 0x989680;\n\t"
            "@P1 bra.uni WD_%=;\n\t"
            "bra.uni WL_%=;\n\t"
            "WD_%=:\n\t}" :: "r"(mbar), "r"(parity) : "memory");
    }
}

// Persistent double-buffered TMA streaming kernel.
// 456 CTAs, each loops over tiles (4 contiguous rows / 32KB per tile), issuing the
// next tile's bulk copies before consuming the current stage. Per-CTA loss sum
// accumulated in registers; one float written per CTA.
__global__ __launch_bounds__(256)
void mvce_persist_kernel(const float* __restrict__ outp, const float* __restrict__ tgtp)
{
    extern __shared__ char smem[];
    float* s_red = reinterpret_cast<float*>(smem + SMEM_RED_OFF);

    const int tid  = threadIdx.x;
    const int lane = tid & 31;
    const int w    = tid >> 5;
    const int pair = w >> 1;          // row within tile (0..3)
    const int half = w & 1;

    const unsigned bar0 = smem_u32(smem + SMEM_BARS_OFF);
    const unsigned bar1 = bar0 + 8;

    if (tid == 0) {
        asm volatile("mbarrier.init.shared.b64 [%0], 1;" :: "r"(bar0) : "memory");
        asm volatile("mbarrier.init.shared.b64 [%0], 1;" :: "r"(bar1) : "memory");
    }
    __syncthreads();

    const ull LOG2E2 = pk2(LOG2E_F, LOG2E_F);
    float ctaAcc = 0.f;               // meaningful on (half==0 && lane==0) threads

    int tile = blockIdx.x;

    // Prologue: fill stage 0.
    if (tid == 0) {
        asm volatile("mbarrier.arrive.expect_tx.shared.b64 _, [%0], %1;"
                     :: "r"(bar0), "r"(2 * TILE_BYTES) : "memory");
        const float* so = outp + (size_t)tile * TILE_FLOATS;
        const float* st = tgtp + (size_t)tile * TILE_FLOATS;
        asm volatile("cp.async.bulk.shared::cta.global.mbarrier::complete_tx::bytes [%0], [%1], %2, [%3];"
                     :: "r"(smem_u32(smem)), "l"(so), "r"(TILE_BYTES), "r"(bar0) : "memory");
        asm volatile("cp.async.bulk.shared::cta.global.mbarrier::complete_tx::bytes [%0], [%1], %2, [%3];"
                     :: "r"(smem_u32(smem) + TILE_BYTES), "l"(st), "r"(TILE_BYTES), "r"(bar0) : "memory");
    }

    for (int it = 0; tile < NTILES; tile += GRID_P, ++it) {
        const int s = it & 1;
        const unsigned barS = s ? bar1 : bar0;

        // Issue next tile into the other stage (consumed at it-1, synced).
        const int nxt = tile + GRID_P;
        if (tid == 0 && nxt < NTILES) {
            const unsigned barN = s ? bar0 : bar1;
            const unsigned dst = smem_u32(smem) + (s ^ 1) * 2 * TILE_BYTES;
            asm volatile("mbarrier.arrive.expect_tx.shared.b64 _, [%0], %1;"
                         :: "r"(barN), "r"(2 * TILE_BYTES) : "memory");
            const float* so = outp + (size_t)nxt * TILE_FLOATS;
            const float* st = tgtp + (size_t)nxt * TILE_FLOATS;
            asm volatile("cp.async.bulk.shared::cta.global.mbarrier::complete_tx::bytes [%0], [%1], %2, [%3];"
                         :: "r"(dst), "l"(so), "r"(TILE_BYTES), "r"(barN) : "memory");
            asm volatile("cp.async.bulk.shared::cta.global.mbarrier::complete_tx::bytes [%0], [%1], %2, [%3];"
                         :: "r"(dst + TILE_BYTES), "l"(st), "r"(TILE_BYTES), "r"(barN) : "memory");
        }

        mbar_wait(barS, (it >> 1) & 1);

        const float* s_o = reinterpret_cast<const float*>(smem + s * 2 * TILE_BYTES);
        const float* s_t = s_o + TILE_FLOATS;
        const float4* o4 = reinterpret_cast<const float4*>(s_o) + pair * 250 + half * 125;
        const float4* t4 = reinterpret_cast<const float4*>(s_t) + pair * 250 + half * 125;

        ull Sall2 = 0, Tall2 = 0, TO2 = 0, E12 = 0, F12 = 0, TOp2 = 0, Tpos2 = 0, np2 = 0;

        #pragma unroll
        for (int k = 0; k < 4; k++) {
            float4 o, t;
            if (k < 3 || lane < 29) {
                o = o4[lane + k * 32];
                t = t4[lane + k * 32];
            } else {
                o = make_float4(-1e30f, -1e30f, -1e30f, -1e30f);   // ex2 -> 0
                t = make_float4(0.f, 0.f, 0.f, 0.f);               // mask 0, negative
            }
            #pragma unroll
            for (int h = 0; h < 2; h++) {
                const float oa = h ? o.z : o.x;
                const float ob = h ? o.w : o.y;
                const float ta = h ? t.z : t.x;
                const float tb = h ? t.w : t.y;

                const ull oo = pk2(oa, ob);
                const ull tt = pk2(ta, tb);

                float xa, xb;
                upk2(mul2(oo, LOG2E2), xa, xb);
                const ull ee = pk2(ex2f(xa), ex2f(xb));
                const ull mm = pk2(rintf(ta), rintf(tb));

                const ull to = mul2(tt, oo);
                const ull te = mul2(tt, ee);

                Sall2 = add2(Sall2, ee);
                Tall2 = add2(Tall2, tt);
                TO2   = add2(TO2, to);
                E12   = fma2(mm, ee, E12);
                F12   = fma2(mm, te, F12);
                TOp2  = fma2(mm, to, TOp2);
                Tpos2 = fma2(mm, tt, Tpos2);
                np2   = add2(np2, mm);
            }
        }

        float a0, a1;
        upk2(Sall2, a0, a1); float Sall = a0 + a1;
        upk2(Tall2, a0, a1); float Tall = a0 + a1;
        upk2(TO2,   a0, a1); float TO   = a0 + a1;
        upk2(E12,   a0, a1); float E1   = a0 + a1;
        upk2(F12,   a0, a1); float F1   = a0 + a1;
        upk2(TOp2,  a0, a1); float TOp  = a0 + a1;
        upk2(Tpos2, a0, a1); float Tpos = a0 + a1;
        upk2(np2,   a0, a1); float np   = a0 + a1;

        Sall = warpSum(Sall); Tall = warpSum(Tall); TO = warpSum(TO);
        E1 = warpSum(E1); F1 = warpSum(F1); TOp = warpSum(TOp);
        Tpos = warpSum(Tpos); np = warpSum(np);

        if (lane == 0) {
            float* r = s_red + w * 8;
            r[0] = Sall; r[1] = Tall; r[2] = TO;  r[3] = E1;
            r[4] = F1;   r[5] = TOp;  r[6] = Tpos; r[7] = np;
        }
        __syncthreads();   // also: all tile reads done -> stage may be overwritten next iter

        if (half == 0 && lane == 0) {
            const float* p = s_red + (w ^ 1) * 8;
            Sall += p[0]; Tall += p[1]; TO   += p[2]; E1 += p[3];
            F1   += p[4]; TOp  += p[5]; Tpos += p[6]; np += p[7];

            const float S = Sall - E1;
            const float T = Tall - Tpos;
            const float A = TO - TOp;
            const float r = __fdividef(1.0f, S);
            const float L = __logf(S);

            float rl;
            if (np > 0.f) {
                const float PL = L * fmaf(np, T, Tpos) + r * fmaf(T, E1, F1);
                rl = (PL - (np - 1.0f) * A - TO) / np;
            } else {
                rl = T * L - A;
            }
            ctaAcc += rl;
        }
        __syncthreads();   // protect s_red against next iteration's writes
    }

    // Per-CTA total: 4 row-owner threads (w=0,2,4,6, lane 0) hold partial sums.
    if (half == 0 && lane == 0) s_red[(w >> 1)] = ctaAcc;
    __syncthreads();
    if (tid == 0)
        g_partial[blockIdx.x] = (s_red[0] + s_red[1]) + (s_red[2] + s_red[3]);
}

// Final: sum 456 per-CTA partials, divide by B. Deterministic.
__global__ __launch_bounds__(512)
void mvce_final_kernel(float* __restrict__ result)
{
    __shared__ float s[16];
    const int tid  = threadIdx.x;
    const int lane = tid & 31;
    const int wid  = tid >> 5;

    float acc = (tid < GRID_P) ? g_partial[tid] : 0.f;
    acc = warpSum(acc);
    if (lane == 0) s[wid] = acc;
    __syncthreads();
    if (tid < 16) {
        float x = s[tid];
        #pragma unroll
        for (int k = 8; k; k >>= 1) x += __shfl_xor_sync(0xffffu, x, k);
        if (tid == 0) result[0] = x / (float)B_ROWS;
    }
}

extern "C" void kernel_launch(void* const* d_in, const int* in_sizes, int n_in,
                              void* d_out, int out_size)
{
    const float* output = (const float*)d_in[0];
    const float* target = (const float*)d_in[1];
    float* result = (float*)d_out;

    cudaFuncSetAttribute(mvce_persist_kernel,
                         cudaFuncAttributeMaxDynamicSharedMemorySize, SMEM_DYN);

    mvce_persist_kernel<<<GRID_P, 256, SMEM_DYN>>>(output, target);
    mvce_final_kernel<<<1, 512>>>(result);
}

// round 14
// speedup vs baseline: 1.0163x; 1.0163x over previous
#include <cuda_runtime.h>
#include <math.h>

#define B_ROWS 65536
#define C_COLS 1000
#define ROWS_PER_TILE 4
#define TILE_FLOATS (ROWS_PER_TILE * C_COLS)     // 4000
#define TILE_BYTES  (TILE_FLOATS * 4)            // 16000 per tensor
#define NTILES (B_ROWS / ROWS_PER_TILE)          // 16384
#define GRID_P 456                                // 3 CTAs/SM x 152 SMs
#define LOG2E_F 1.4426950408889634f

// Dynamic smem layout (bytes):
//   stage s in {0,1}: o at s*2*TILE_BYTES, t at s*2*TILE_BYTES + TILE_BYTES
//   bars at 4*TILE_BYTES (2 x u64), red (double-buffered 2x8x8 floats) after
#define SMEM_BARS_OFF (4 * TILE_BYTES)
#define SMEM_RED_OFF  (SMEM_BARS_OFF + 16)
#define SMEM_DYN      (SMEM_RED_OFF + 2 * 8 * 8 * 4)

__device__ float g_partial[GRID_P];
__device__ unsigned g_count;                      // zero-init; reset by last CTA each run

typedef unsigned long long ull;

__device__ __forceinline__ ull pk2(float lo, float hi) {
    ull r; asm("mov.b64 %0, {%1, %2};" : "=l"(r) : "f"(lo), "f"(hi)); return r;
}
__device__ __forceinline__ void upk2(ull v, float& lo, float& hi) {
    asm("mov.b64 {%0, %1}, %2;" : "=f"(lo), "=f"(hi) : "l"(v));
}
__device__ __forceinline__ ull mul2(ull a, ull b) {
    ull d; asm("mul.rn.f32x2 %0, %1, %2;" : "=l"(d) : "l"(a), "l"(b)); return d;
}
__device__ __forceinline__ ull add2(ull a, ull b) {
    ull d; asm("add.rn.f32x2 %0, %1, %2;" : "=l"(d) : "l"(a), "l"(b)); return d;
}
__device__ __forceinline__ ull fma2(ull a, ull b, ull c) {
    ull d; asm("fma.rn.f32x2 %0, %1, %2, %3;" : "=l"(d) : "l"(a), "l"(b), "l"(c)); return d;
}
__device__ __forceinline__ float ex2f(float x) {
    float r; asm("ex2.approx.ftz.f32 %0, %1;" : "=f"(r) : "f"(x)); return r;
}
__device__ __forceinline__ unsigned smem_u32(const void* p) {
    unsigned a;
    asm("{ .reg .u64 t; cvta.to.shared.u64 t, %1; cvt.u32.u64 %0, t; }" : "=r"(a) : "l"(p));
    return a;
}
__device__ __forceinline__ float warpSum(float v) {
    #pragma unroll
    for (int k = 16; k; k >>= 1) v += __shfl_xor_sync(0xffffffffu, v, k);
    return v;
}
__device__ __forceinline__ void mbar_wait(unsigned mbar, unsigned parity) {
    unsigned done;
    asm volatile(
        "{\n\t.reg .pred p;\n\t"
        "mbarrier.try_wait.parity.acquire.cta.shared::cta.b64 p, [%1], %2;\n\t"
        "selp.b32 %0, 1, 0, p;\n\t}"
        : "=r"(done) : "r"(mbar), "r"(parity) : "memory");
    if (!done) {
        asm volatile(
            "{\n\t.reg .pred P1;\n\t"
            "WL_%=:\n\t"
            "mbarrier.try_wait.parity.acquire.cta.shared::cta.b64 P1, [%0], %1, 0x989680;\n\t"
            "@P1 bra.uni WD_%=;\n\t"
            "bra.uni WL_%=;\n\t"
            "WD_%=:\n\t}" :: "r"(mbar), "r"(parity) : "memory");
    }
}

// Persistent double-buffered TMA streaming kernel with FUSED final reduction
// (last-CTA pattern). Single launch; deterministic (fixed summation orders).
__global__ __launch_bounds__(256)
void mvce_persist_kernel(const float* __restrict__ outp, const float* __restrict__ tgtp,
                         float* __restrict__ result)
{
    extern __shared__ char smem[];
    float* s_redbase = reinterpret_cast<float*>(smem + SMEM_RED_OFF);   // [2][8][8]

    const int tid  = threadIdx.x;
    const int lane = tid & 31;
    const int w    = tid >> 5;
    const int pair = w >> 1;          // row within tile (0..3)
    const int half = w & 1;

    const unsigned bar0 = smem_u32(smem + SMEM_BARS_OFF);
    const unsigned bar1 = bar0 + 8;

    if (tid == 0) {
        asm volatile("mbarrier.init.shared.b64 [%0], 1;" :: "r"(bar0) : "memory");
        asm volatile("mbarrier.init.shared.b64 [%0], 1;" :: "r"(bar1) : "memory");
    }
    __syncthreads();

    const ull LOG2E2 = pk2(LOG2E_F, LOG2E_F);
    float ctaAcc = 0.f;               // meaningful on (half==0 && lane==0) threads

    int tile = blockIdx.x;

    // Prologue: fill stage 0.
    if (tid == 0) {
        asm volatile("mbarrier.arrive.expect_tx.shared.b64 _, [%0], %1;"
                     :: "r"(bar0), "r"(2 * TILE_BYTES) : "memory");
        const float* so = outp + (size_t)tile * TILE_FLOATS;
        const float* st = tgtp + (size_t)tile * TILE_FLOATS;
        asm volatile("cp.async.bulk.shared::cta.global.mbarrier::complete_tx::bytes [%0], [%1], %2, [%3];"
                     :: "r"(smem_u32(smem)), "l"(so), "r"(TILE_BYTES), "r"(bar0) : "memory");
        asm volatile("cp.async.bulk.shared::cta.global.mbarrier::complete_tx::bytes [%0], [%1], %2, [%3];"
                     :: "r"(smem_u32(smem) + TILE_BYTES), "l"(st), "r"(TILE_BYTES), "r"(bar0) : "memory");
    }

    for (int it = 0; tile < NTILES; tile += GRID_P, ++it) {
        const int s = it & 1;
        const unsigned barS = s ? bar1 : bar0;
        float* s_red = s_redbase + s * 64;

        // Issue next tile into the other stage (fully consumed: barrier at end of it-1).
        const int nxt = tile + GRID_P;
        if (tid == 0 && nxt < NTILES) {
            const unsigned barN = s ? bar0 : bar1;
            const unsigned dst = smem_u32(smem) + (s ^ 1) * 2 * TILE_BYTES;
            asm volatile("mbarrier.arrive.expect_tx.shared.b64 _, [%0], %1;"
                         :: "r"(barN), "r"(2 * TILE_BYTES) : "memory");
            const float* so = outp + (size_t)nxt * TILE_FLOATS;
            const float* st = tgtp + (size_t)nxt * TILE_FLOATS;
            asm volatile("cp.async.bulk.shared::cta.global.mbarrier::complete_tx::bytes [%0], [%1], %2, [%3];"
                         :: "r"(dst), "l"(so), "r"(TILE_BYTES), "r"(barN) : "memory");
            asm volatile("cp.async.bulk.shared::cta.global.mbarrier::complete_tx::bytes [%0], [%1], %2, [%3];"
                         :: "r"(dst + TILE_BYTES), "l"(st), "r"(TILE_BYTES), "r"(barN) : "memory");
        }

        mbar_wait(barS, (it >> 1) & 1);

        const float* s_o = reinterpret_cast<const float*>(smem + s * 2 * TILE_BYTES);
        const float* s_t = s_o + TILE_FLOATS;
        const float4* o4 = reinterpret_cast<const float4*>(s_o) + pair * 250 + half * 125;
        const float4* t4 = reinterpret_cast<const float4*>(s_t) + pair * 250 + half * 125;

        ull Sall2 = 0, Tall2 = 0, TO2 = 0, E12 = 0, F12 = 0, TOp2 = 0, Tpos2 = 0, np2 = 0;

        #pragma unroll
        for (int k = 0; k < 4; k++) {
            float4 o, t;
            if (k < 3 || lane < 29) {
                o = o4[lane + k * 32];
                t = t4[lane + k * 32];
            } else {
                o = make_float4(-1e30f, -1e30f, -1e30f, -1e30f);   // ex2 -> 0
                t = make_float4(0.f, 0.f, 0.f, 0.f);               // mask 0, negative
            }
            #pragma unroll
            for (int h = 0; h < 2; h++) {
                const float oa = h ? o.z : o.x;
                const float ob = h ? o.w : o.y;
                const float ta = h ? t.z : t.x;
                const float tb = h ? t.w : t.y;

                const ull oo = pk2(oa, ob);
                const ull tt = pk2(ta, tb);

                float xa, xb;
                upk2(mul2(oo, LOG2E2), xa, xb);
                const ull ee = pk2(ex2f(xa), ex2f(xb));
                const ull mm = pk2(rintf(ta), rintf(tb));

                const ull to = mul2(tt, oo);
                const ull te = mul2(tt, ee);

                Sall2 = add2(Sall2, ee);
                Tall2 = add2(Tall2, tt);
                TO2   = add2(TO2, to);
                E12   = fma2(mm, ee, E12);
                F12   = fma2(mm, te, F12);
                TOp2  = fma2(mm, to, TOp2);
                Tpos2 = fma2(mm, tt, Tpos2);
                np2   = add2(np2, mm);
            }
        }

        float a0, a1;
        upk2(Sall2, a0, a1); float Sall = a0 + a1;
        upk2(Tall2, a0, a1); float Tall = a0 + a1;
        upk2(TO2,   a0, a1); float TO   = a0 + a1;
        upk2(E12,   a0, a1); float E1   = a0 + a1;
        upk2(F12,   a0, a1); float F1   = a0 + a1;
        upk2(TOp2,  a0, a1); float TOp  = a0 + a1;
        upk2(Tpos2, a0, a1); float Tpos = a0 + a1;
        upk2(np2,   a0, a1); float np   = a0 + a1;

        Sall = warpSum(Sall); Tall = warpSum(Tall); TO = warpSum(TO);
        E1 = warpSum(E1); F1 = warpSum(F1); TOp = warpSum(TOp);
        Tpos = warpSum(Tpos); np = warpSum(np);

        if (lane == 0) {
            float* r = s_red + w * 8;
            r[0] = Sall; r[1] = Tall; r[2] = TO;  r[3] = E1;
            r[4] = F1;   r[5] = TOp;  r[6] = Tpos; r[7] = np;
        }
        __syncthreads();   // single barrier per tile: orders red buffer + stage reuse

        if (half == 0 && lane == 0) {
            const float* p = s_red + (w ^ 1) * 8;
            Sall += p[0]; Tall += p[1]; TO   += p[2]; E1 += p[3];
            F1   += p[4]; TOp  += p[5]; Tpos += p[6]; np += p[7];

            const float S = Sall - E1;
            const float T = Tall - Tpos;
            const float A = TO - TOp;
            const float r = __fdividef(1.0f, S);
            const float L = __logf(S);

            float rl;
            if (np > 0.f) {
                const float PL = L * fmaf(np, T, Tpos) + r * fmaf(T, E1, F1);
                rl = (PL - (np - 1.0f) * A - TO) / np;
            } else {
                rl = T * L - A;
            }
            ctaAcc += rl;
        }
        // no second barrier: next iteration uses the other red buffer; the one
        // barrier per iteration prevents any warp from being 2 iterations ahead.
    }

    // Per-CTA total -> g_partial[blockIdx.x]; last CTA reduces all partials.
    if (half == 0 && lane == 0) s_redbase[(w >> 1)] = ctaAcc;
    __syncthreads();
    if (tid == 0) {
        g_partial[blockIdx.x] = (s_redbase[0] + s_redbase[1]) + (s_redbase[2] + s_redbase[3]);
        __threadfence();
        unsigned old = atomicAdd(&g_count, 1u);
        s_redbase[4] = (old == GRID_P - 1) ? 1.f : 0.f;
    }
    __syncthreads();

    if (s_redbase[4] != 0.f) {
        // This CTA is last: all g_partial[] writes are visible (fence+atomic chain).
        __threadfence();
        float acc = 0.f;
        if (tid < GRID_P) acc = g_partial[tid];
        if (tid + 256 < GRID_P) acc += g_partial[tid + 256];
        acc = warpSum(acc);
        if (lane == 0) s_redbase[8 + w] = acc;
        __syncthreads();
        if (tid == 0) {
            float x = ((s_redbase[8] + s_redbase[9]) + (s_redbase[10] + s_redbase[11]))
                    + ((s_redbase[12] + s_redbase[13]) + (s_redbase[14] + s_redbase[15]));
            result[0] = x / (float)B_ROWS;
            g_count = 0;           // reset for next graph replay (deterministic)
        }
    }
}

extern "C" void kernel_launch(void* const* d_in, const int* in_sizes, int n_in,
                              void* d_out, int out_size)
{
    const float* output = (const float*)d_in[0];
    const float* target = (const float*)d_in[1];
    float* result = (float*)d_out;

    cudaFuncSetAttribute(mvce_persist_kernel,
                         cudaFuncAttributeMaxDynamicSharedMemorySize, SMEM_DYN);

    mvce_persist_kernel<<<GRID_P, 256, SMEM_DYN>>>(output, target, result);
}